// round 6
// baseline (speedup 1.0000x reference)
#include <cuda_runtime.h>
#include <cuda_bf16.h>
#include <cstdint>

// Problem constants (fixed by the dataset)
#define N_NODES_MAX 50000
#define E_MAX       550000
#define B_MAX       4096
#define F           128
#define H           512
#define CAP         128      // per-slot neighbor bucket capacity (P(deg>128) ~ 0)

// Scratch (static device globals — no allocation allowed)
__device__ int            g_flag[N_NODES_MAX];   // 0 = unmarked, else slot+1
__device__ int            g_deg[B_MAX];          // in-degree per slot (bucket cursor)
__device__ int            g_bkt[B_MAX * CAP];    // fixed-stride neighbor buckets
__device__ __nv_bfloat16  g_h_hi[B_MAX * F];     // h_neigh split: high bf16
__device__ __nv_bfloat16  g_h_lo[B_MAX * F];     // h_neigh split: low  bf16
__device__ __nv_bfloat16  g_w_hi[H * F];         // W split: high bf16
__device__ __nv_bfloat16  g_w_lo[H * F];         // W split: low  bf16

// ---------------------------------------------------------------------------
// helpers
__device__ __forceinline__ uint32_t smem_u32(const void* p) {
    return (uint32_t)__cvta_generic_to_shared(p);
}
__device__ __forceinline__ uint32_t pack_bf2(__nv_bfloat16 a, __nv_bfloat16 b) {
    __nv_bfloat162 t; t.x = a; t.y = b;
    return *reinterpret_cast<uint32_t*>(&t);
}

#define LDSM_X4(R, PTR)                                                        \
    asm volatile("ldmatrix.sync.aligned.m8n8.x4.shared.b16 {%0,%1,%2,%3}, [%4];" \
                 : "=r"((R)[0]), "=r"((R)[1]), "=r"((R)[2]), "=r"((R)[3])       \
                 : "r"(smem_u32(PTR)))

#define MMA_BF16(C, A, B0, B1)                                                 \
    asm volatile("mma.sync.aligned.m16n8k16.row.col.f32.bf16.bf16.f32 "        \
                 "{%0,%1,%2,%3}, {%4,%5,%6,%7}, {%8,%9}, {%0,%1,%2,%3};"       \
                 : "+f"((C)[0]), "+f"((C)[1]), "+f"((C)[2]), "+f"((C)[3])      \
                 : "r"((A)[0]), "r"((A)[1]), "r"((A)[2]), "r"((A)[3]),         \
                   "r"(B0), "r"(B1))

__device__ __forceinline__ float fast_tanh(float x) {
    asm("tanh.approx.f32 %0, %0;" : "+f"(x));
    return x;
}

// ---------------------------------------------------------------------------
// K0: clear node flags AND split W into bf16 hi/lo (independent work, one launch)
__global__ void k_reset(int n_nodes, const float* __restrict__ W) {
    int i = blockIdx.x * blockDim.x + threadIdx.x;
    int stride = gridDim.x * blockDim.x;
    for (int idx = i; idx < n_nodes; idx += stride) g_flag[idx] = 0;
    for (int idx = i; idx < H * F; idx += stride) {
        float w = W[idx];
        __nv_bfloat16 hi = __float2bfloat16(w);
        g_w_hi[idx] = hi;
        g_w_lo[idx] = __float2bfloat16(w - __bfloat162float(hi));
    }
}

// K1: mark id nodes with their slot (+1) AND zero per-slot degree counters.
// Duplicate ids: arbitrary winner; all readers resolve through g_flag.
__global__ void k_mark(const int* __restrict__ ids, int nb) {
    int i = blockIdx.x * blockDim.x + threadIdx.x;
    if (i < nb) {
        g_flag[ids[i]] = i + 1;
        g_deg[i] = 0;
    }
}

// K2: scan all edges (dst vectorized); edges landing on marked nodes go
// straight into the destination slot's fixed-stride bucket. src is only
// read for the ~8% of edges that hit a marked node.
__device__ __forceinline__ void scan_one(const int* __restrict__ src, int j, int d) {
    int f = g_flag[d];
    if (f > 0) {
        int slot = f - 1;
        int pos = atomicAdd(&g_deg[slot], 1);
        if (pos < CAP) g_bkt[slot * CAP + pos] = src[j];
    }
}
__global__ void k_scan(const int* __restrict__ src, const int* __restrict__ dst, int ne) {
    int i = blockIdx.x * blockDim.x + threadIdx.x;
    int ne4 = ne >> 2;
    if (i < ne4) {
        int4 d = ((const int4*)dst)[i];
        scan_one(src, 4 * i + 0, d.x);
        scan_one(src, 4 * i + 1, d.y);
        scan_one(src, 4 * i + 2, d.z);
        scan_one(src, 4 * i + 3, d.w);
    }
    int tail = ne & 3;
    if (i < tail) {
        int j = ne - tail + i;
        scan_one(src, j, dst[j]);
    }
}

// K3: TWO warps per output row (each owns 64 features, float2/lane) for 2x
// latency hiding. Sum bucket neighbor rows in registers, add feat[v],
// scale by 1/(deg+1), write bf16 hi/lo split rows. No atomics.
__global__ void k_slotsum(const float* __restrict__ feat,
                          const int* __restrict__ ids, int nb) {
    int gtid = blockIdx.x * blockDim.x + threadIdx.x;
    int gw   = gtid >> 5;              // global warp id
    int w    = gw >> 1;                // output row
    int half = gw & 1;                 // feature half (0: 0..63, 1: 64..127)
    int lane = threadIdx.x & 31;
    if (w >= nb) return;

    int node = ids[w];
    int slot = g_flag[node] - 1;       // winner slot (handles duplicate ids)
    int deg  = g_deg[slot];
    int cnt  = deg < CAP ? deg : CAP;
    const int* bkt = g_bkt + slot * CAP;

    int fofs = half * 64 + lane * 2;   // this lane's 2 features
    float2 acc = *(const float2*)(feat + (size_t)node * F + fofs);  // + feat[v]

    int e = 0;
    for (; e + 8 <= cnt; e += 8) {
        int si[8];
        #pragma unroll
        for (int u = 0; u < 8; u++) si[u] = bkt[e + u];
        float2 v[8];
        #pragma unroll
        for (int u = 0; u < 8; u++)
            v[u] = *(const float2*)(feat + (size_t)si[u] * F + fofs);
        #pragma unroll
        for (int u = 0; u < 8; u++) { acc.x += v[u].x; acc.y += v[u].y; }
    }
    for (; e + 4 <= cnt; e += 4) {
        int s0 = bkt[e], s1 = bkt[e+1], s2 = bkt[e+2], s3 = bkt[e+3];
        float2 v0 = *(const float2*)(feat + (size_t)s0 * F + fofs);
        float2 v1 = *(const float2*)(feat + (size_t)s1 * F + fofs);
        float2 v2 = *(const float2*)(feat + (size_t)s2 * F + fofs);
        float2 v3 = *(const float2*)(feat + (size_t)s3 * F + fofs);
        acc.x += v0.x + v1.x + v2.x + v3.x;
        acc.y += v0.y + v1.y + v2.y + v3.y;
    }
    for (; e < cnt; e++) {
        float2 v = *(const float2*)(feat + (size_t)bkt[e] * F + fofs);
        acc.x += v.x; acc.y += v.y;
    }

    float inv = 1.0f / (float)(deg + 1);
    acc.x *= inv; acc.y *= inv;

    // bf16 hi/lo split, 2 values per lane, packed 4B stores
    __nv_bfloat16 hx = __float2bfloat16(acc.x);
    __nv_bfloat16 hy = __float2bfloat16(acc.y);
    *(uint32_t*)(g_h_hi + (size_t)w * F + fofs) = pack_bf2(hx, hy);
    *(uint32_t*)(g_h_lo + (size_t)w * F + fofs) =
        pack_bf2(__float2bfloat16(acc.x - __bfloat162float(hx)),
                 __float2bfloat16(acc.y - __bfloat162float(hy)));
}

// K4: tensor-core GEMM with bf16 3-split: out = tanh(h @ W^T + bias).
// BM=BN=64, K=128 in two 64-chunks. 8 warps: warp_m = wid&1 (m32),
// warp_n = wid>>1 (n16). mma.m16n8k16, hi*hi + hi*lo + lo*hi.
__global__ void k_gemm(const float* __restrict__ bias, float* __restrict__ out, int nb) {
    __shared__ __nv_bfloat16 a_hi[64][72], a_lo[64][72];
    __shared__ __nv_bfloat16 b_hi[64][72], b_lo[64][72];

    int tid  = threadIdx.x;
    int wid  = tid >> 5, lane = tid & 31;
    int warp_m = wid & 1, warp_n = wid >> 1;
    int rowBase = blockIdx.y * 64, colBase = blockIdx.x * 64;
    int g8 = lane >> 3, r8 = lane & 7;

    float acc[2][2][4] = {};

    #pragma unroll
    for (int kc = 0; kc < 2; kc++) {
        // stage 64x64 tiles of all four operands (uint4 = 8 bf16)
        #pragma unroll
        for (int l = 0; l < 2; l++) {
            int idx = tid + l * 256;
            int rr = idx >> 3, c8 = (idx & 7) * 8;
            int gc = kc * 64 + c8;
            *(uint4*)&a_hi[rr][c8] = *(const uint4*)&g_h_hi[(size_t)(rowBase + rr) * F + gc];
            *(uint4*)&a_lo[rr][c8] = *(const uint4*)&g_h_lo[(size_t)(rowBase + rr) * F + gc];
            *(uint4*)&b_hi[rr][c8] = *(const uint4*)&g_w_hi[(size_t)(colBase + rr) * F + gc];
            *(uint4*)&b_lo[rr][c8] = *(const uint4*)&g_w_lo[(size_t)(colBase + rr) * F + gc];
        }
        __syncthreads();

        #pragma unroll
        for (int ks = 0; ks < 64; ks += 16) {
            uint32_t ah[2][4], al[2][4], bh[4], bl[4];
            #pragma unroll
            for (int mt = 0; mt < 2; mt++) {
                int row = warp_m * 32 + mt * 16 + (g8 & 1) * 8 + r8;
                int col = ks + (g8 >> 1) * 8;
                LDSM_X4(ah[mt], &a_hi[row][col]);
                LDSM_X4(al[mt], &a_lo[row][col]);
            }
            {
                int brow = warp_n * 16 + (g8 >> 1) * 8 + r8;
                int bcol = ks + (g8 & 1) * 8;
                LDSM_X4(bh, &b_hi[brow][bcol]);
                LDSM_X4(bl, &b_lo[brow][bcol]);
            }
            #pragma unroll
            for (int mt = 0; mt < 2; mt++)
                #pragma unroll
                for (int nt = 0; nt < 2; nt++) {
                    MMA_BF16(acc[mt][nt], ah[mt], bh[2*nt], bh[2*nt+1]);
                    MMA_BF16(acc[mt][nt], ah[mt], bl[2*nt], bl[2*nt+1]);
                    MMA_BF16(acc[mt][nt], al[mt], bh[2*nt], bh[2*nt+1]);
                }
        }
        __syncthreads();
    }

    // epilogue: +bias, tanh, store
    int g = lane >> 2, t = lane & 3;
    #pragma unroll
    for (int mt = 0; mt < 2; mt++) {
        int row0 = rowBase + warp_m * 32 + mt * 16 + g;
        #pragma unroll
        for (int nt = 0; nt < 2; nt++) {
            int col = colBase + warp_n * 16 + nt * 8 + t * 2;
            float2 b = *(const float2*)(bias + col);
            float2 o0, o1;
            o0.x = fast_tanh(acc[mt][nt][0] + b.x);
            o0.y = fast_tanh(acc[mt][nt][1] + b.y);
            o1.x = fast_tanh(acc[mt][nt][2] + b.x);
            o1.y = fast_tanh(acc[mt][nt][3] + b.y);
            if (row0 < nb)     *(float2*)(out + (size_t)row0 * H + col) = o0;
            if (row0 + 8 < nb) *(float2*)(out + (size_t)(row0 + 8) * H + col) = o1;
        }
    }
}

// ---------------------------------------------------------------------------
extern "C" void kernel_launch(void* const* d_in, const int* in_sizes, int n_in,
                              void* d_out, int out_size) {
    const float* feat = (const float*)d_in[0];   // [N, 128]
    const float* W    = (const float*)d_in[1];   // [512, 128]
    const float* bias = (const float*)d_in[2];   // [512]
    const int*   src  = (const int*)d_in[3];     // [E]
    const int*   dst  = (const int*)d_in[4];     // [E]
    const int*   ids  = (const int*)d_in[5];     // [B]

    int n_nodes = in_sizes[0] / F;
    int ne      = in_sizes[3];
    int nb      = in_sizes[5];

    k_reset<<<128, 256>>>(n_nodes, W);
    k_mark<<<(nb + 255) / 256, 256>>>(ids, nb);
    int nthr = (ne + 3) / 4;
    k_scan<<<(nthr + 255) / 256, 256>>>(src, dst, ne);
    k_slotsum<<<(nb * 64 + 255) / 256, 256>>>(feat, ids, nb);   // 2 warps/row
    dim3 ggrid(H / 64, (nb + 63) / 64);
    k_gemm<<<ggrid, 256>>>(bias, (float*)d_out, nb);
}

// round 7
// speedup vs baseline: 1.1104x; 1.1104x over previous
#include <cuda_runtime.h>
#include <cuda_bf16.h>
#include <cstdint>

// Problem constants (fixed by the dataset)
#define N_NODES_MAX 50000
#define E_MAX       550000
#define B_MAX       4096
#define F           128
#define H           512
#define CAP         128      // per-slot neighbor bucket capacity (P(deg>128) ~ 0)

// Scratch (static device globals — zero-initialized at module load; the
// flag/deg invariant (all zero) is restored by k_gemm's cleanup each call)
__device__ int            g_flag[N_NODES_MAX];   // 0 = unmarked, else slot+1
__device__ int            g_deg[B_MAX];          // in-degree per slot (bucket cursor)
__device__ int            g_bkt[B_MAX * CAP];    // fixed-stride neighbor buckets
__device__ __nv_bfloat16  g_h_hi[B_MAX * F];     // h_neigh split: high bf16
__device__ __nv_bfloat16  g_h_lo[B_MAX * F];     // h_neigh split: low  bf16
__device__ __nv_bfloat16  g_w_hi[H * F];         // W split: high bf16
__device__ __nv_bfloat16  g_w_lo[H * F];         // W split: low  bf16

// ---------------------------------------------------------------------------
// helpers
__device__ __forceinline__ uint32_t smem_u32(const void* p) {
    return (uint32_t)__cvta_generic_to_shared(p);
}
__device__ __forceinline__ uint32_t pack_bf2(__nv_bfloat16 a, __nv_bfloat16 b) {
    __nv_bfloat162 t; t.x = a; t.y = b;
    return *reinterpret_cast<uint32_t*>(&t);
}

#define LDSM_X4(R, PTR)                                                        \
    asm volatile("ldmatrix.sync.aligned.m8n8.x4.shared.b16 {%0,%1,%2,%3}, [%4];" \
                 : "=r"((R)[0]), "=r"((R)[1]), "=r"((R)[2]), "=r"((R)[3])       \
                 : "r"(smem_u32(PTR)))

#define MMA_BF16(C, A, B0, B1)                                                 \
    asm volatile("mma.sync.aligned.m16n8k16.row.col.f32.bf16.bf16.f32 "        \
                 "{%0,%1,%2,%3}, {%4,%5,%6,%7}, {%8,%9}, {%0,%1,%2,%3};"       \
                 : "+f"((C)[0]), "+f"((C)[1]), "+f"((C)[2]), "+f"((C)[3])      \
                 : "r"((A)[0]), "r"((A)[1]), "r"((A)[2]), "r"((A)[3]),         \
                   "r"(B0), "r"(B1))

__device__ __forceinline__ float fast_tanh(float x) {
    asm("tanh.approx.f32 %0, %0;" : "+f"(x));
    return x;
}

// ---------------------------------------------------------------------------
// K1: mark id nodes with slot (+1) AND split W into bf16 hi/lo.
// deg counters are already zero (module-load init / previous call's cleanup).
__global__ void k_mark(const int* __restrict__ ids, int nb,
                       const float* __restrict__ W) {
    int i = blockIdx.x * blockDim.x + threadIdx.x;
    int stride = gridDim.x * blockDim.x;
    if (i < nb) g_flag[ids[i]] = i + 1;
    for (int idx = i; idx < H * F; idx += stride) {
        float w = W[idx];
        __nv_bfloat16 hi = __float2bfloat16(w);
        g_w_hi[idx] = hi;
        g_w_lo[idx] = __float2bfloat16(w - __bfloat162float(hi));
    }
    cudaTriggerProgrammaticLaunchCompletion();
}

// K2: scan all edges; edges landing on marked nodes go straight into the
// destination slot's fixed-stride bucket. dst vector load is the PDL
// prologue (input buffer, safe before the grid sync).
__device__ __forceinline__ void scan_one(const int* __restrict__ src, int j, int d) {
    int f = g_flag[d];
    if (f > 0) {
        int slot = f - 1;
        int pos = atomicAdd(&g_deg[slot], 1);
        if (pos < CAP) g_bkt[slot * CAP + pos] = src[j];
    }
}
__global__ void k_scan(const int* __restrict__ src, const int* __restrict__ dst, int ne) {
    int i = blockIdx.x * blockDim.x + threadIdx.x;
    int ne4 = ne >> 2;
    int4 d = make_int4(0, 0, 0, 0);
    if (i < ne4) d = ((const int4*)dst)[i];           // prologue load
    int tail = ne & 3;
    int tj = -1, td = 0;
    if (i < tail) { tj = ne - tail + i; td = dst[tj]; }

    cudaGridDependencySynchronize();                   // wait for k_mark

    if (i < ne4) {
        scan_one(src, 4 * i + 0, d.x);
        scan_one(src, 4 * i + 1, d.y);
        scan_one(src, 4 * i + 2, d.z);
        scan_one(src, 4 * i + 3, d.w);
    }
    if (tj >= 0) scan_one(src, tj, td);
    cudaTriggerProgrammaticLaunchCompletion();
}

// K3: TWO warps per output row (64 features each, float2/lane). Single
// predicated 16-wide gather batch (one dependent-load round covers deg<=16,
// ~97% of rows); rare spill loop after. PDL prologue: ids + self feat.
__global__ void k_slotsum(const float* __restrict__ feat,
                          const int* __restrict__ ids, int nb) {
    int gtid = blockIdx.x * blockDim.x + threadIdx.x;
    int gw   = gtid >> 5;              // global warp id
    int w    = gw >> 1;                // output row
    int half = gw & 1;                 // feature half (0: 0..63, 1: 64..127)
    int lane = threadIdx.x & 31;
    if (w >= nb) return;

    int node = ids[w];
    int fofs = half * 64 + lane * 2;   // this lane's 2 features
    float2 acc = *(const float2*)(feat + (size_t)node * F + fofs);  // + feat[v]

    cudaGridDependencySynchronize();   // wait for k_scan (buckets complete)

    int slot = g_flag[node] - 1;       // winner slot (handles duplicate ids)
    int deg  = g_deg[slot];
    int cnt  = deg < CAP ? deg : CAP;
    const int* bkt = g_bkt + slot * CAP;

    int m = cnt < 16 ? cnt : 16;
    float2 v[16];
    #pragma unroll
    for (int u = 0; u < 16; u++) {
        if (u < m) {
            int s = bkt[u];
            v[u] = *(const float2*)(feat + (size_t)s * F + fofs);
        } else {
            v[u] = make_float2(0.0f, 0.0f);
        }
    }
    #pragma unroll
    for (int u = 0; u < 16; u++) { acc.x += v[u].x; acc.y += v[u].y; }
    for (int e = 16; e < cnt; e++) {   // rare (P(deg>16) ~ 3%)
        float2 t = *(const float2*)(feat + (size_t)bkt[e] * F + fofs);
        acc.x += t.x; acc.y += t.y;
    }

    float inv = 1.0f / (float)(deg + 1);
    acc.x *= inv; acc.y *= inv;

    // bf16 hi/lo split, 2 values per lane, packed 4B stores
    __nv_bfloat16 hx = __float2bfloat16(acc.x);
    __nv_bfloat16 hy = __float2bfloat16(acc.y);
    *(uint32_t*)(g_h_hi + (size_t)w * F + fofs) = pack_bf2(hx, hy);
    *(uint32_t*)(g_h_lo + (size_t)w * F + fofs) =
        pack_bf2(__float2bfloat16(acc.x - __bfloat162float(hx)),
                 __float2bfloat16(acc.y - __bfloat162float(hy)));
    cudaTriggerProgrammaticLaunchCompletion();
}

// K4: tensor-core GEMM with bf16 3-split: out = tanh(h @ W^T + bias).
// BM=BN=64, K=128 in two 64-chunks. PDL prologue: stage kc=0 W tiles.
// Also restores the g_flag/g_deg all-zero invariant for the next call.
__global__ void k_gemm(const float* __restrict__ bias, float* __restrict__ out,
                       int nb, const int* __restrict__ ids) {
    __shared__ __nv_bfloat16 a_hi[64][72], a_lo[64][72];
    __shared__ __nv_bfloat16 b_hi[64][72], b_lo[64][72];

    int tid  = threadIdx.x;
    int wid  = tid >> 5, lane = tid & 31;
    int warp_m = wid & 1, warp_n = wid >> 1;
    int rowBase = blockIdx.y * 64, colBase = blockIdx.x * 64;
    int g8 = lane >> 3, r8 = lane & 7;

    // prologue: stage kc=0 B (W) tiles — written by k_mark, which fully
    // completed >=2 grid boundaries upstream
    #pragma unroll
    for (int l = 0; l < 2; l++) {
        int idx = tid + l * 256;
        int rr = idx >> 3, c8 = (idx & 7) * 8;
        *(uint4*)&b_hi[rr][c8] = *(const uint4*)&g_w_hi[(size_t)(colBase + rr) * F + c8];
        *(uint4*)&b_lo[rr][c8] = *(const uint4*)&g_w_lo[(size_t)(colBase + rr) * F + c8];
    }

    cudaGridDependencySynchronize();   // wait for k_slotsum (g_h ready)

    // cleanup: restore flag/deg zero-invariant (flags no longer needed)
    int fbid = blockIdx.y * gridDim.x + blockIdx.x;
    int cid  = fbid * 256 + tid;
    if (cid < nb) {
        g_flag[ids[cid]] = 0;
        g_deg[cid] = 0;
    }

    float acc[2][2][4] = {};

    #pragma unroll
    for (int kc = 0; kc < 2; kc++) {
        // stage A tiles (and B tiles for kc=1)
        #pragma unroll
        for (int l = 0; l < 2; l++) {
            int idx = tid + l * 256;
            int rr = idx >> 3, c8 = (idx & 7) * 8;
            int gc = kc * 64 + c8;
            *(uint4*)&a_hi[rr][c8] = *(const uint4*)&g_h_hi[(size_t)(rowBase + rr) * F + gc];
            *(uint4*)&a_lo[rr][c8] = *(const uint4*)&g_h_lo[(size_t)(rowBase + rr) * F + gc];
            if (kc == 1) {
                *(uint4*)&b_hi[rr][c8] = *(const uint4*)&g_w_hi[(size_t)(colBase + rr) * F + gc];
                *(uint4*)&b_lo[rr][c8] = *(const uint4*)&g_w_lo[(size_t)(colBase + rr) * F + gc];
            }
        }
        __syncthreads();

        #pragma unroll
        for (int ks = 0; ks < 64; ks += 16) {
            uint32_t ah[2][4], al[2][4], bh[4], bl[4];
            #pragma unroll
            for (int mt = 0; mt < 2; mt++) {
                int row = warp_m * 32 + mt * 16 + (g8 & 1) * 8 + r8;
                int col = ks + (g8 >> 1) * 8;
                LDSM_X4(ah[mt], &a_hi[row][col]);
                LDSM_X4(al[mt], &a_lo[row][col]);
            }
            {
                int brow = warp_n * 16 + (g8 >> 1) * 8 + r8;
                int bcol = ks + (g8 & 1) * 8;
                LDSM_X4(bh, &b_hi[brow][bcol]);
                LDSM_X4(bl, &b_lo[brow][bcol]);
            }
            #pragma unroll
            for (int mt = 0; mt < 2; mt++)
                #pragma unroll
                for (int nt = 0; nt < 2; nt++) {
                    MMA_BF16(acc[mt][nt], ah[mt], bh[2*nt], bh[2*nt+1]);
                    MMA_BF16(acc[mt][nt], ah[mt], bl[2*nt], bl[2*nt+1]);
                    MMA_BF16(acc[mt][nt], al[mt], bh[2*nt], bh[2*nt+1]);
                }
        }
        __syncthreads();
    }

    // epilogue: +bias, tanh, store
    int g = lane >> 2, t = lane & 3;
    #pragma unroll
    for (int mt = 0; mt < 2; mt++) {
        int row0 = rowBase + warp_m * 32 + mt * 16 + g;
        #pragma unroll
        for (int nt = 0; nt < 2; nt++) {
            int col = colBase + warp_n * 16 + nt * 8 + t * 2;
            float2 b = *(const float2*)(bias + col);
            float2 o0, o1;
            o0.x = fast_tanh(acc[mt][nt][0] + b.x);
            o0.y = fast_tanh(acc[mt][nt][1] + b.y);
            o1.x = fast_tanh(acc[mt][nt][2] + b.x);
            o1.y = fast_tanh(acc[mt][nt][3] + b.y);
            if (row0 < nb)     *(float2*)(out + (size_t)row0 * H + col) = o0;
            if (row0 + 8 < nb) *(float2*)(out + (size_t)(row0 + 8) * H + col) = o1;
        }
    }
}

// ---------------------------------------------------------------------------
template <typename... Args>
static inline void launch_pdl(void (*kern)(Args...), dim3 grid, dim3 block,
                              Args... args) {
    cudaLaunchConfig_t cfg = {};
    cfg.gridDim = grid;
    cfg.blockDim = block;
    cfg.dynamicSmemBytes = 0;
    cfg.stream = 0;
    cudaLaunchAttribute attr[1];
    attr[0].id = cudaLaunchAttributeProgrammaticStreamSerialization;
    attr[0].val.programmaticStreamSerializationAllowed = 1;
    cfg.attrs = attr;
    cfg.numAttrs = 1;
    cudaLaunchKernelEx(&cfg, kern, args...);
}

extern "C" void kernel_launch(void* const* d_in, const int* in_sizes, int n_in,
                              void* d_out, int out_size) {
    const float* feat = (const float*)d_in[0];   // [N, 128]
    const float* W    = (const float*)d_in[1];   // [512, 128]
    const float* bias = (const float*)d_in[2];   // [512]
    const int*   src  = (const int*)d_in[3];     // [E]
    const int*   dst  = (const int*)d_in[4];     // [E]
    const int*   ids  = (const int*)d_in[5];     // [B]

    int ne = in_sizes[3];
    int nb = in_sizes[5];

    k_mark<<<256, 256>>>(ids, nb, W);
    int nthr = (ne + 3) / 4;
    launch_pdl(k_scan, dim3((nthr + 255) / 256), dim3(256), src, dst, ne);
    launch_pdl(k_slotsum, dim3((nb * 64 + 255) / 256), dim3(256), feat, ids, nb);
    launch_pdl(k_gemm, dim3(H / 64, (nb + 63) / 64), dim3(256),
               bias, (float*)d_out, nb, ids);
}

// round 9
// speedup vs baseline: 1.2877x; 1.1596x over previous
#include <cuda_runtime.h>
#include <cuda_fp16.h>
#include <cstdint>

// Problem constants (fixed by the dataset)
#define N_NODES_MAX 50000
#define E_MAX       550000
#define B_MAX       4096
#define F           128
#define H           512
#define CAP         128      // per-slot neighbor bucket capacity (P(deg>128) ~ 0)

// Scratch (static device globals — zero-initialized at module load; the
// flag/deg invariant (all zero) is restored by k_gemm's cleanup each call)
__device__ int    g_flag[N_NODES_MAX];   // 0 = unmarked, else slot+1
__device__ int    g_deg[B_MAX];          // in-degree per slot (bucket cursor)
__device__ int    g_bkt[B_MAX * CAP];    // fixed-stride neighbor buckets
__device__ __half g_h[B_MAX * F];        // h_neigh rows, fp16
__device__ __half g_w_hi[H * F];         // W split: high fp16
__device__ __half g_w_lo[H * F];         // W split: low  fp16 (residual)

// ---------------------------------------------------------------------------
// helpers
__device__ __forceinline__ uint32_t smem_u32(const void* p) {
    return (uint32_t)__cvta_generic_to_shared(p);
}
__device__ __forceinline__ uint32_t pack_h2(float a, float b) {
    __half2 t = __floats2half2_rn(a, b);
    return *reinterpret_cast<uint32_t*>(&t);
}
__device__ __forceinline__ float fast_tanh(float x) {
    asm("tanh.approx.f32 %0, %0;" : "+f"(x));
    return x;
}

#define LDSM_X4(R, PTR)                                                        \
    asm volatile("ldmatrix.sync.aligned.m8n8.x4.shared.b16 {%0,%1,%2,%3}, [%4];" \
                 : "=r"((R)[0]), "=r"((R)[1]), "=r"((R)[2]), "=r"((R)[3])       \
                 : "r"(smem_u32(PTR)))

#define MMA_F16(C, A, B0, B1)                                                  \
    asm volatile("mma.sync.aligned.m16n8k16.row.col.f32.f16.f16.f32 "          \
                 "{%0,%1,%2,%3}, {%4,%5,%6,%7}, {%8,%9}, {%0,%1,%2,%3};"       \
                 : "+f"((C)[0]), "+f"((C)[1]), "+f"((C)[2]), "+f"((C)[3])      \
                 : "r"((A)[0]), "r"((A)[1]), "r"((A)[2]), "r"((A)[3]),         \
                   "r"(B0), "r"(B1))

// ---------------------------------------------------------------------------
// K1: mark id nodes with slot (+1) AND split W into fp16 hi/lo.
// deg counters are already zero (module-load init / previous call's cleanup).
__global__ void k_mark(const int* __restrict__ ids, int nb,
                       const float* __restrict__ W) {
    int i = blockIdx.x * blockDim.x + threadIdx.x;
    int stride = gridDim.x * blockDim.x;
    if (i < nb) g_flag[ids[i]] = i + 1;
    for (int idx = i; idx < H * F; idx += stride) {
        float w = W[idx];
        __half hi = __float2half_rn(w);
        g_w_hi[idx] = hi;
        g_w_lo[idx] = __float2half_rn(w - __half2float(hi));
    }
    cudaTriggerProgrammaticLaunchCompletion();
}

// K2: scan all edges; marked-dst edges go into the slot's bucket.
// dst vector load is the PDL prologue (input buffer, safe pre-gridsync).
__device__ __forceinline__ void scan_one(const int* __restrict__ src, int j, int d) {
    int f = g_flag[d];
    if (f > 0) {
        int slot = f - 1;
        int pos = atomicAdd(&g_deg[slot], 1);
        if (pos < CAP) g_bkt[slot * CAP + pos] = src[j];
    }
}
__global__ void k_scan(const int* __restrict__ src, const int* __restrict__ dst, int ne) {
    int i = blockIdx.x * blockDim.x + threadIdx.x;
    int ne4 = ne >> 2;
    int4 d = make_int4(0, 0, 0, 0);
    if (i < ne4) d = ((const int4*)dst)[i];           // prologue load
    int tail = ne & 3;
    int tj = -1, td = 0;
    if (i < tail) { tj = ne - tail + i; td = dst[tj]; }

    cudaGridDependencySynchronize();                   // wait for k_mark

    if (i < ne4) {
        scan_one(src, 4 * i + 0, d.x);
        scan_one(src, 4 * i + 1, d.y);
        scan_one(src, 4 * i + 2, d.z);
        scan_one(src, 4 * i + 3, d.w);
    }
    if (tj >= 0) scan_one(src, tj, td);
    cudaTriggerProgrammaticLaunchCompletion();
}

// K3: TWO warps per output row (64 features each, float2/lane). Single
// predicated 16-wide gather batch; rare spill loop. fp16 output.
__global__ void k_slotsum(const float* __restrict__ feat,
                          const int* __restrict__ ids, int nb) {
    int gtid = blockIdx.x * blockDim.x + threadIdx.x;
    int gw   = gtid >> 5;
    int w    = gw >> 1;
    int half_ = gw & 1;
    int lane = threadIdx.x & 31;
    if (w >= nb) return;

    int node = ids[w];
    int fofs = half_ * 64 + lane * 2;
    float2 acc = *(const float2*)(feat + (size_t)node * F + fofs);  // + feat[v]

    cudaGridDependencySynchronize();   // wait for k_scan

    int slot = g_flag[node] - 1;       // winner slot (handles duplicate ids)
    int deg  = g_deg[slot];
    int cnt  = deg < CAP ? deg : CAP;
    const int* bkt = g_bkt + slot * CAP;

    int m = cnt < 16 ? cnt : 16;
    float2 v[16];
    #pragma unroll
    for (int u = 0; u < 16; u++) {
        if (u < m) {
            int s = bkt[u];
            v[u] = *(const float2*)(feat + (size_t)s * F + fofs);
        } else {
            v[u] = make_float2(0.0f, 0.0f);
        }
    }
    #pragma unroll
    for (int u = 0; u < 16; u++) { acc.x += v[u].x; acc.y += v[u].y; }
    for (int e = 16; e < cnt; e++) {   // rare (P(deg>16) ~ 3%)
        float2 t = *(const float2*)(feat + (size_t)bkt[e] * F + fofs);
        acc.x += t.x; acc.y += t.y;
    }

    float inv = 1.0f / (float)(deg + 1);
    *(uint32_t*)(g_h + (size_t)w * F + fofs) = pack_h2(acc.x * inv, acc.y * inv);
    cudaTriggerProgrammaticLaunchCompletion();
}

// ---------------------------------------------------------------------------
// K4: fp16 2-MMA-split tensor GEMM: out = tanh(h @ (W_hi+W_lo)^T + bias).
// BM=BN=64, full K=128 staged once (3 tiles, 52KB dynamic smem, 1 sync).
// 8 warps: warp_m = wid&1 (m32), warp_n = wid>>1 (n16). mma.m16n8k16.f16.
#define TROW 136                         // padded row stride (halfs)
#define TSZ  (64 * TROW)                 // halfs per tile
#define SM_BYTES (3 * TSZ * 2)

__global__ void __launch_bounds__(256)
k_gemm(const float* __restrict__ bias, float* __restrict__ out,
       int nb, const int* __restrict__ ids) {
    extern __shared__ __half sm[];
    __half* sa  = sm;                    // h tile      [64][136]
    __half* sbh = sm + TSZ;              // W_hi tile   [64][136]
    __half* sbl = sm + 2 * TSZ;          // W_lo tile   [64][136]

    int tid  = threadIdx.x;
    int wid  = tid >> 5, lane = tid & 31;
    int warp_m = wid & 1, warp_n = wid >> 1;
    int rowBase = blockIdx.y * 64, colBase = blockIdx.x * 64;
    int g8 = lane >> 3, r8 = lane & 7;

    // PDL prologue: stage W tiles (k_mark fully completed >=2 launches upstream)
    #pragma unroll
    for (int it = 0; it < 4; it++) {
        int idx = tid + it * 256;        // 0..1023 uint4s per tile
        int r = idx >> 4, u = idx & 15;  // row, 8-half unit
        *(uint4*)&sbh[r * TROW + u * 8] = *(const uint4*)&g_w_hi[(size_t)(colBase + r) * F + u * 8];
        *(uint4*)&sbl[r * TROW + u * 8] = *(const uint4*)&g_w_lo[(size_t)(colBase + r) * F + u * 8];
    }

    cudaGridDependencySynchronize();     // wait for k_slotsum (g_h ready)

    // cleanup: restore flag/deg zero-invariant for the next graph replay
    int cid = (blockIdx.y * gridDim.x + blockIdx.x) * 256 + tid;
    if (cid < nb) {
        g_flag[ids[cid]] = 0;
        g_deg[cid] = 0;
    }

    #pragma unroll
    for (int it = 0; it < 4; it++) {
        int idx = tid + it * 256;
        int r = idx >> 4, u = idx & 15;
        *(uint4*)&sa[r * TROW + u * 8] = *(const uint4*)&g_h[(size_t)(rowBase + r) * F + u * 8];
    }
    __syncthreads();

    float acc[2][2][4] = {};

    #pragma unroll
    for (int ks = 0; ks < 128; ks += 16) {
        uint32_t a[2][4], bh[4], bl[4];
        #pragma unroll
        for (int mt = 0; mt < 2; mt++) {
            int row = warp_m * 32 + mt * 16 + (g8 & 1) * 8 + r8;
            int col = ks + (g8 >> 1) * 8;
            LDSM_X4(a[mt], &sa[row * TROW + col]);
        }
        {
            int brow = warp_n * 16 + (g8 >> 1) * 8 + r8;
            int bcol = ks + (g8 & 1) * 8;
            LDSM_X4(bh, &sbh[brow * TROW + bcol]);
            LDSM_X4(bl, &sbl[brow * TROW + bcol]);
        }
        #pragma unroll
        for (int mt = 0; mt < 2; mt++)
            #pragma unroll
            for (int nt = 0; nt < 2; nt++) {
                MMA_F16(acc[mt][nt], a[mt], bh[2*nt], bh[2*nt+1]);
                MMA_F16(acc[mt][nt], a[mt], bl[2*nt], bl[2*nt+1]);
            }
    }

    // epilogue: +bias, tanh, store
    int g = lane >> 2, t = lane & 3;
    #pragma unroll
    for (int mt = 0; mt < 2; mt++) {
        int row0 = rowBase + warp_m * 32 + mt * 16 + g;
        #pragma unroll
        for (int nt = 0; nt < 2; nt++) {
            int col = colBase + warp_n * 16 + nt * 8 + t * 2;
            float2 b = *(const float2*)(bias + col);
            float2 o0, o1;
            o0.x = fast_tanh(acc[mt][nt][0] + b.x);
            o0.y = fast_tanh(acc[mt][nt][1] + b.y);
            o1.x = fast_tanh(acc[mt][nt][2] + b.x);
            o1.y = fast_tanh(acc[mt][nt][3] + b.y);
            if (row0 < nb)     *(float2*)(out + (size_t)row0 * H + col) = o0;
            if (row0 + 8 < nb) *(float2*)(out + (size_t)(row0 + 8) * H + col) = o1;
        }
    }
}

// ---------------------------------------------------------------------------
template <typename... Args>
static inline void launch_pdl(void (*kern)(Args...), dim3 grid, dim3 block,
                              size_t smem, Args... args) {
    cudaLaunchConfig_t cfg = {};
    cfg.gridDim = grid;
    cfg.blockDim = block;
    cfg.dynamicSmemBytes = smem;
    cfg.stream = 0;
    cudaLaunchAttribute attr[1];
    attr[0].id = cudaLaunchAttributeProgrammaticStreamSerialization;
    attr[0].val.programmaticStreamSerializationAllowed = 1;
    cfg.attrs = attr;
    cfg.numAttrs = 1;
    cudaLaunchKernelEx(&cfg, kern, args...);
}

extern "C" void kernel_launch(void* const* d_in, const int* in_sizes, int n_in,
                              void* d_out, int out_size) {
    const float* feat = (const float*)d_in[0];   // [N, 128]
    const float* W    = (const float*)d_in[1];   // [512, 128]
    const float* bias = (const float*)d_in[2];   // [512]
    const int*   src  = (const int*)d_in[3];     // [E]
    const int*   dst  = (const int*)d_in[4];     // [E]
    const int*   ids  = (const int*)d_in[5];     // [B]

    int ne = in_sizes[3];
    int nb = in_sizes[5];

    static bool attr_set = false;
    if (!attr_set) {
        cudaFuncSetAttribute(k_gemm, cudaFuncAttributeMaxDynamicSharedMemorySize,
                             SM_BYTES);
        attr_set = true;
    }

    k_mark<<<256, 256>>>(ids, nb, W);
    int nthr = (ne + 3) / 4;
    launch_pdl(k_scan, dim3((nthr + 255) / 256), dim3(256), (size_t)0, src, dst, ne);
    launch_pdl(k_slotsum, dim3((nb * 64 + 255) / 256), dim3(256), (size_t)0, feat, ids, nb);
    launch_pdl(k_gemm, dim3(H / 64, (nb + 63) / 64), dim3(256), (size_t)SM_BYTES,
               bias, (float*)d_out, nb, ids);
}

// round 10
// speedup vs baseline: 1.4250x; 1.1067x over previous
#include <cuda_runtime.h>
#include <cuda_fp16.h>
#include <cstdint>

// Problem constants (fixed by the dataset)
#define N_NODES_MAX 50000
#define E_MAX       550000
#define B_MAX       4096
#define F           128
#define H           512
#define CAP         128      // per-slot neighbor bucket capacity (P(deg>128) ~ 0)

// Scratch (static device globals — zero-initialized at module load; the
// flag/deg invariant (all zero) is restored by k_gemm's cleanup each call)
__device__ int    g_flag[N_NODES_MAX];   // 0 = unmarked, else slot+1
__device__ int    g_deg[B_MAX];          // in-degree per slot (bucket cursor)
__device__ int    g_bkt[B_MAX * CAP];    // fixed-stride neighbor buckets
__device__ __half g_h[B_MAX * F];        // h_neigh rows, fp16
__device__ __half g_w[H * F];            // W, fp16

// ---------------------------------------------------------------------------
// helpers
__device__ __forceinline__ uint32_t smem_u32(const void* p) {
    return (uint32_t)__cvta_generic_to_shared(p);
}
__device__ __forceinline__ uint32_t pack_h2(float a, float b) {
    __half2 t = __floats2half2_rn(a, b);
    return *reinterpret_cast<uint32_t*>(&t);
}
__device__ __forceinline__ float fast_tanh(float x) {
    asm("tanh.approx.f32 %0, %0;" : "+f"(x));
    return x;
}

#define LDSM_X4(R, PTR)                                                        \
    asm volatile("ldmatrix.sync.aligned.m8n8.x4.shared.b16 {%0,%1,%2,%3}, [%4];" \
                 : "=r"((R)[0]), "=r"((R)[1]), "=r"((R)[2]), "=r"((R)[3])       \
                 : "r"(smem_u32(PTR)))

#define MMA_F16(C, A, B0, B1)                                                  \
    asm volatile("mma.sync.aligned.m16n8k16.row.col.f32.f16.f16.f32 "          \
                 "{%0,%1,%2,%3}, {%4,%5,%6,%7}, {%8,%9}, {%0,%1,%2,%3};"       \
                 : "+f"((C)[0]), "+f"((C)[1]), "+f"((C)[2]), "+f"((C)[3])      \
                 : "r"((A)[0]), "r"((A)[1]), "r"((A)[2]), "r"((A)[3]),         \
                   "r"(B0), "r"(B1))

// ---------------------------------------------------------------------------
// K1: mark id nodes with slot (+1) AND convert W to fp16.
// deg counters are already zero (module-load init / previous call's cleanup).
__global__ void k_mark(const int* __restrict__ ids, int nb,
                       const float* __restrict__ W) {
    int i = blockIdx.x * blockDim.x + threadIdx.x;
    int stride = gridDim.x * blockDim.x;
    if (i < nb) g_flag[ids[i]] = i + 1;
    for (int idx = i; idx < H * F; idx += stride)
        g_w[idx] = __float2half_rn(W[idx]);
    cudaTriggerProgrammaticLaunchCompletion();
}

// K2: scan all edges; marked-dst edges go into the slot's bucket.
// dst vector load is the PDL prologue (input buffer, safe pre-gridsync).
__device__ __forceinline__ void scan_one(const int* __restrict__ src, int j, int d) {
    int f = g_flag[d];
    if (f > 0) {
        int slot = f - 1;
        int pos = atomicAdd(&g_deg[slot], 1);
        if (pos < CAP) g_bkt[slot * CAP + pos] = src[j];
    }
}
__global__ void k_scan(const int* __restrict__ src, const int* __restrict__ dst, int ne) {
    int i = blockIdx.x * blockDim.x + threadIdx.x;
    int ne4 = ne >> 2;
    int4 d = make_int4(0, 0, 0, 0);
    if (i < ne4) d = ((const int4*)dst)[i];           // prologue load
    int tail = ne & 3;
    int tj = -1, td = 0;
    if (i < tail) { tj = ne - tail + i; td = dst[tj]; }

    cudaGridDependencySynchronize();                   // wait for k_mark

    if (i < ne4) {
        scan_one(src, 4 * i + 0, d.x);
        scan_one(src, 4 * i + 1, d.y);
        scan_one(src, 4 * i + 2, d.z);
        scan_one(src, 4 * i + 3, d.w);
    }
    if (tj >= 0) scan_one(src, tj, td);
    cudaTriggerProgrammaticLaunchCompletion();
}

// K3: TWO warps per output row (64 features each, float2/lane). Single
// predicated 16-wide gather batch; rare spill loop. fp16 output.
__global__ void k_slotsum(const float* __restrict__ feat,
                          const int* __restrict__ ids, int nb) {
    int gtid = blockIdx.x * blockDim.x + threadIdx.x;
    int gw   = gtid >> 5;
    int w    = gw >> 1;
    int half_ = gw & 1;
    int lane = threadIdx.x & 31;
    if (w >= nb) return;

    int node = ids[w];
    int fofs = half_ * 64 + lane * 2;
    float2 acc = *(const float2*)(feat + (size_t)node * F + fofs);  // + feat[v]

    cudaGridDependencySynchronize();   // wait for k_scan

    int slot = g_flag[node] - 1;       // winner slot (handles duplicate ids)
    int deg  = g_deg[slot];
    int cnt  = deg < CAP ? deg : CAP;
    const int* bkt = g_bkt + slot * CAP;

    int m = cnt < 16 ? cnt : 16;
    float2 v[16];
    #pragma unroll
    for (int u = 0; u < 16; u++) {
        if (u < m) {
            int s = bkt[u];
            v[u] = *(const float2*)(feat + (size_t)s * F + fofs);
        } else {
            v[u] = make_float2(0.0f, 0.0f);
        }
    }
    #pragma unroll
    for (int u = 0; u < 16; u++) { acc.x += v[u].x; acc.y += v[u].y; }
    for (int e = 16; e < cnt; e++) {   // rare (P(deg>16) ~ 3%)
        float2 t = *(const float2*)(feat + (size_t)bkt[e] * F + fofs);
        acc.x += t.x; acc.y += t.y;
    }

    float inv = 1.0f / (float)(deg + 1);
    *(uint32_t*)(g_h + (size_t)w * F + fofs) = pack_h2(acc.x * inv, acc.y * inv);
    cudaTriggerProgrammaticLaunchCompletion();
}

// ---------------------------------------------------------------------------
// K4: fp16 tensor GEMM: out = tanh(h @ W^T + bias).
// BM=128, BN=64, full K=128 staged once. 8 warps in 2x4 (m,n) grid,
// warp tile m32n32: per k-step 4 LDSM : 8 MMA. Grid (H/64, nb/128).
#define TROW 136                         // padded row stride (halfs)
#define A_TSZ (128 * TROW)
#define B_TSZ (64 * TROW)
#define SM_BYTES ((A_TSZ + B_TSZ) * 2)

__global__ void __launch_bounds__(256)
k_gemm(const float* __restrict__ bias, float* __restrict__ out,
       int nb, const int* __restrict__ ids) {
    extern __shared__ __half sm[];
    __half* sa = sm;                     // h tile [128][136]
    __half* sb = sm + A_TSZ;             // W tile  [64][136]

    int tid  = threadIdx.x;
    int wid  = tid >> 5, lane = tid & 31;
    int warp_m = wid & 1, warp_n = wid >> 1;   // m: 2x64... see below
    // Warp grid: 4 warps along M (m32 each), 2 along N (n32 each)
    int wm = wid & 3;          // 0..3 -> m32 tile
    int wn = wid >> 2;         // 0..1 -> n32 tile
    (void)warp_m; (void)warp_n;
    int rowBase = blockIdx.y * 128, colBase = blockIdx.x * 64;
    int g8 = lane >> 3, r8 = lane & 7;

    // PDL prologue: stage W tile (k_mark fully completed >=2 launches upstream)
    #pragma unroll
    for (int it = 0; it < 4; it++) {
        int idx = tid + it * 256;        // 0..1023 uint4s
        int r = idx >> 4, u = idx & 15;
        *(uint4*)&sb[r * TROW + u * 8] = *(const uint4*)&g_w[(size_t)(colBase + r) * F + u * 8];
    }

    cudaGridDependencySynchronize();     // wait for k_slotsum (g_h ready)

    // cleanup: restore flag/deg zero-invariant for the next graph replay
    int cid = (blockIdx.y * gridDim.x + blockIdx.x) * 256 + tid;
    if (cid < nb) {
        g_flag[ids[cid]] = 0;
        g_deg[cid] = 0;
    }

    #pragma unroll
    for (int it = 0; it < 8; it++) {
        int idx = tid + it * 256;        // 0..2047 uint4s
        int r = idx >> 4, u = idx & 15;
        *(uint4*)&sa[r * TROW + u * 8] = *(const uint4*)&g_h[(size_t)(rowBase + r) * F + u * 8];
    }
    __syncthreads();

    float acc[2][4][4] = {};             // [mt][nt][reg]

    #pragma unroll
    for (int ks = 0; ks < 128; ks += 16) {
        uint32_t a[2][4], b[2][4];
        #pragma unroll
        for (int mt = 0; mt < 2; mt++) {
            int row = wm * 32 + mt * 16 + (g8 & 1) * 8 + r8;
            int col = ks + (g8 >> 1) * 8;
            LDSM_X4(a[mt], &sa[row * TROW + col]);
        }
        #pragma unroll
        for (int bt = 0; bt < 2; bt++) {
            int brow = wn * 32 + bt * 16 + (g8 >> 1) * 8 + r8;
            int bcol = ks + (g8 & 1) * 8;
            LDSM_X4(b[bt], &sb[brow * TROW + bcol]);
        }
        #pragma unroll
        for (int mt = 0; mt < 2; mt++)
            #pragma unroll
            for (int bt = 0; bt < 2; bt++) {
                MMA_F16(acc[mt][bt * 2 + 0], a[mt], b[bt][0], b[bt][1]);
                MMA_F16(acc[mt][bt * 2 + 1], a[mt], b[bt][2], b[bt][3]);
            }
    }

    // epilogue: +bias, tanh, store
    int g = lane >> 2, t = lane & 3;
    #pragma unroll
    for (int mt = 0; mt < 2; mt++) {
        int row0 = rowBase + wm * 32 + mt * 16 + g;
        #pragma unroll
        for (int nt = 0; nt < 4; nt++) {
            int col = colBase + wn * 32 + nt * 8 + t * 2;
            float2 b = *(const float2*)(bias + col);
            float2 o0, o1;
            o0.x = fast_tanh(acc[mt][nt][0] + b.x);
            o0.y = fast_tanh(acc[mt][nt][1] + b.y);
            o1.x = fast_tanh(acc[mt][nt][2] + b.x);
            o1.y = fast_tanh(acc[mt][nt][3] + b.y);
            if (row0 < nb)     *(float2*)(out + (size_t)row0 * H + col) = o0;
            if (row0 + 8 < nb) *(float2*)(out + (size_t)(row0 + 8) * H + col) = o1;
        }
    }
}

// ---------------------------------------------------------------------------
template <typename... Args>
static inline void launch_pdl(void (*kern)(Args...), dim3 grid, dim3 block,
                              size_t smem, Args... args) {
    cudaLaunchConfig_t cfg = {};
    cfg.gridDim = grid;
    cfg.blockDim = block;
    cfg.dynamicSmemBytes = smem;
    cfg.stream = 0;
    cudaLaunchAttribute attr[1];
    attr[0].id = cudaLaunchAttributeProgrammaticStreamSerialization;
    attr[0].val.programmaticStreamSerializationAllowed = 1;
    cfg.attrs = attr;
    cfg.numAttrs = 1;
    cudaLaunchKernelEx(&cfg, kern, args...);
}

extern "C" void kernel_launch(void* const* d_in, const int* in_sizes, int n_in,
                              void* d_out, int out_size) {
    const float* feat = (const float*)d_in[0];   // [N, 128]
    const float* W    = (const float*)d_in[1];   // [512, 128]
    const float* bias = (const float*)d_in[2];   // [512]
    const int*   src  = (const int*)d_in[3];     // [E]
    const int*   dst  = (const int*)d_in[4];     // [E]
    const int*   ids  = (const int*)d_in[5];     // [B]

    int ne = in_sizes[3];
    int nb = in_sizes[5];

    static bool attr_set = false;
    if (!attr_set) {
        cudaFuncSetAttribute(k_gemm, cudaFuncAttributeMaxDynamicSharedMemorySize,
                             SM_BYTES);
        attr_set = true;
    }

    k_mark<<<256, 256>>>(ids, nb, W);
    int nthr = (ne + 3) / 4;
    launch_pdl(k_scan, dim3((nthr + 255) / 256), dim3(256), (size_t)0, src, dst, ne);
    launch_pdl(k_slotsum, dim3((nb * 64 + 255) / 256), dim3(256), (size_t)0, feat, ids, nb);
    launch_pdl(k_gemm, dim3(H / 64, (nb + 127) / 128), dim3(256), (size_t)SM_BYTES,
               bias, (float*)d_out, nb, ids);
}